// round 8
// baseline (speedup 1.0000x reference)
#include <cuda_runtime.h>
#include <cstdint>

#define NH 256
#define NL 4096
#define AP 68                  // pitch (floats): mult of 4 (ldmatrix 16B rows), 68%32=4 spreads banks
#define CROFF  (128 * AP)      // E1 -> P/carries region
#define INJOFF (256 * AP)      // injection table r^p in B-operand layout
#define NFLT   (INJOFF + 64 * AP)
#define SMEMF  (NFLT * 4)      // 87040 B dyn -> 2 CTAs/SM

static __device__ __forceinline__ int kperm(int k) {
    return (k & ~7) | ((k & 3) << 1) | ((k >> 2) & 1);
}
static __device__ __forceinline__ uint32_t s2u(const void* p) {
    uint32_t a;
    asm("{ .reg .u64 t; cvta.to.shared.u64 t, %1; cvt.u32.u64 %0, t; }" : "=r"(a) : "l"(p));
    return a;
}
static __device__ __forceinline__ void cpa16(uint32_t dst, const void* src) {
    asm volatile("cp.async.cg.shared.global [%0], [%1], 16;" :: "r"(dst), "l"(src) : "memory");
}
static __device__ __forceinline__ void ldmA(uint32_t* a, uint32_t addr) {
    asm volatile("ldmatrix.sync.aligned.m8n8.x4.shared.b16 {%0,%1,%2,%3}, [%4];"
                 : "=r"(a[0]), "=r"(a[1]), "=r"(a[2]), "=r"(a[3]) : "r"(addr));
}
static __device__ __forceinline__ void mma8(float* c, const uint32_t* a, float bx, float by) {
    asm volatile(
        "mma.sync.aligned.m16n8k8.row.col.f32.tf32.tf32.f32 "
        "{%0,%1,%2,%3},{%4,%5,%6,%7},{%8,%9},{%0,%1,%2,%3};"
        : "+f"(c[0]), "+f"(c[1]), "+f"(c[2]), "+f"(c[3])
        : "r"(a[0]), "r"(a[1]), "r"(a[2]), "r"(a[3]),
          "r"(__float_as_uint(bx)), "r"(__float_as_uint(by)));
}
static __device__ __forceinline__ float2 cmad(float2 m, float2 c, float2 p) {
    float2 r;
    r.x = fmaf(m.x, c.x, fmaf(-m.y, c.y, p.x));
    r.y = fmaf(m.x, c.y, fmaf( m.y, c.x, p.y));
    return r;
}

// ---------------------------------------------------------------------------
// Single fused kernel. CTA = (h, b-pair), M=128 rows, 512 threads (4Mx4N warps).
// SMEM (floats): Us[128][AP] @0 (u), CR[128][AP] @CROFF (E1 rows0-63 -> P/carries),
//                Inj[64][AP] @INJOFF (r^{i+1} in B-operand layout, odd cols = -Im).
// ---------------------------------------------------------------------------
__global__ __launch_bounds__(512, 2) void k_fused(
        const float* __restrict__ u,     const float* __restrict__ theta,
        const float* __restrict__ av_,   const float* __restrict__ Dp,
        const float* __restrict__ b_p,   const float* __restrict__ c_p,
        const float* __restrict__ x0,    float* __restrict__ out) {
    extern __shared__ float sm[];
    float* Us  = sm;
    float* CR  = sm + CROFF;
    float* Inj = sm + INJOFF;
    __shared__ float2 swS[32];
    __shared__ float2 c0S[32];
    __shared__ float  sfX[128];
    __shared__ float2 Sbuf[8][64];
    __shared__ float2 R8S[8][32];   // (r^8)^k, k=1..8, at [k-1][d]

    int tid  = threadIdx.x;
    int lane = tid & 31, warp = tid >> 5;
    int mw = warp & 3, nw = warp >> 2;          // 4(M) x 4(N) warp grid
    int t0n = nw, t1n = 7 - nw;                 // balanced N-tile pair
    int h = blockIdx.x >> 2, b0 = (blockIdx.x & 3) * 2;
    const float T = 1.0f / (float)(NL - 1);
    float Dv = __ldg(&Dp[h]);
    uint32_t sb = s2u(sm);

    // ---- phase 0: async u loads (2048 x 16B) ----
    #pragma unroll
    for (int it = 0; it < 4; it++) {
        int idx = it * 512 + tid;
        int row = idx >> 4, c4 = (idx & 15) << 2;
        const float* src = u + ((size_t)((b0 + (row >> 6)) * NH + h)) * NL
                             + (row & 63) * 64 + c4;
        cpa16(sb + (row * AP + c4) * 4, src);
    }

    // ---- phase A: params + short chains (14 serial cmuls, warp 0 only) ----
    if (tid < 32) {
        int d = tid, idx = h * 32 + d;
        float av = fabsf(av_[idx]);
        float th = theta[idx];
        float er = expf(-av * T);
        float rr = er * cosf(th * T), ri = er * sinf(th * T);
        float den = av * av + th * th;
        float nr = rr - 1.0f, ni = ri;
        float t0r = (nr * -av + ni * th) / den;
        float t0i = (ni * -av - nr * th) / den;
        float q = b_p[idx] * c_p[idx];
        swS[d] = make_float2(2.0f * t0r * q, 2.0f * t0i * q);
        float g = 4.0f * T * c_p[idx] * x0[idx];
        float rm2 = rr * rr + ri * ri;
        c0S[d] = make_float2(g * rr / rm2, -g * ri / rm2);
        int kpE = kperm(2 * d), kpO = kperm(2 * d + 1);
        float pr = rr, pi = ri;
        Inj[kpE] = pr; Inj[kpO] = -pi;
        #pragma unroll
        for (int p = 2; p <= 8; p++) {
            float npr = fmaf(pr, rr, -pi * ri);
            float npi = fmaf(pr, ri,  pi * rr);
            pr = npr; pi = npi;
            Inj[(p - 1) * AP + kpE] = pr;
            Inj[(p - 1) * AP + kpO] = -pi;
        }
        float qr = pr, qi = pi;
        R8S[0][d] = make_float2(qr, qi);
        #pragma unroll
        for (int k = 2; k <= 8; k++) {
            float nqr = fmaf(qr, pr, -qi * pi);
            float nqi = fmaf(qr, pi,  qi * pr);
            qr = nqr; qi = nqi;
            R8S[k - 1][d] = make_float2(qr, qi);
        }
    }
    __syncthreads();

    // ---- phase C: fill Inj rows 8..63 (1792 entries, one cmul each) ----
    #pragma unroll
    for (int it = 0; it < 4; it++) {
        int e = it * 512 + tid;
        if (e < 1792) {
            int i = 8 + (e >> 5), d = e & 31;
            int kpE = kperm(2 * d), kpO = kperm(2 * d + 1);
            int v = i + 1;                        // 9..64
            int k = (v - 1) >> 3, j = v - (k << 3);
            float2 A = R8S[k - 1][d];
            float bRe = Inj[(j - 1) * AP + kpE];
            float bIm = -Inj[(j - 1) * AP + kpO];
            float re = fmaf(A.x, bRe, -A.y * bIm);
            float im = fmaf(A.x, bIm,  A.y * bRe);
            Inj[i * AP + kpE] = re;
            Inj[i * AP + kpO] = -im;
        }
    }
    __syncthreads();

    // ---- E1 tile into CR rows 0-63 (B-operand layout, 2048 entries) ----
    #pragma unroll
    for (int it = 0; it < 4; it++) {
        int e = it * 512 + tid;
        int d = e >> 6, m = e & 63;
        float2 w = swS[d];
        float re, mi;                          // r^{63-m} = (re, -mi)
        if (m == 63) { re = 1.0f; mi = 0.0f; }
        else {
            re = Inj[(62 - m) * AP + kperm(2 * d)];
            mi = Inj[(62 - m) * AP + kperm(2 * d + 1)];
        }
        int col = kperm(m);
        CR[(2 * d) * AP + col]     = fmaf(w.x, re,  w.y * mi);
        CR[(2 * d + 1) * AP + col] = fmaf(w.y, re, -w.x * mi);
    }
    // ---- sfX: zero pad [0,64) + filter f[j] at [64+j] ----
    if (tid < 128) {
        if (tid < 64) sfX[tid] = 0.0f;
        else {
            int j = tid - 64;
            float s = 0.0f;
            if (j == 0) {
                #pragma unroll
                for (int d = 0; d < 32; d++) s += swS[d].x;
            } else {
                #pragma unroll
                for (int d = 0; d < 32; d++) {
                    float2 w = swS[d];
                    s = fmaf(w.x, Inj[(j - 1) * AP + kperm(2 * d)],
                        fmaf(w.y, Inj[(j - 1) * AP + kperm(2 * d + 1)], s));
                }
            }
            sfX[tid] = s;
        }
    }
    asm volatile("cp.async.wait_all;" ::: "memory");
    __syncthreads();

    // ---- fragment addressing ----
    uint32_t aU[2], aC[2];
    #pragma unroll
    for (int mt = 0; mt < 2; mt++) {
        uint32_t off = ((mw * 32 + mt * 16 + (lane & 7) + ((lane >> 3) & 1) * 8) * AP) * 4
                       + ((lane >> 4) & 1) * 16;
        aU[mt] = sb + off;
        aC[mt] = sb + CROFF * 4 + off;
    }
    int bn8   = lane >> 2;
    int bCol2 = 2 * (lane & 3);

    // ---- merged loop: P GEMM (K=64, dense) + Y half2 (u x Toeplitz, triangle) ----
    float pc[2][2][4], yc[2][2][4];
    #pragma unroll
    for (int mt = 0; mt < 2; mt++)
        #pragma unroll
        for (int j = 0; j < 2; j++)
            #pragma unroll
            for (int q = 0; q < 4; q++) { pc[mt][j][q] = 0.0f; yc[mt][j][q] = 0.0f; }

    #pragma unroll
    for (int ks = 0; ks < 8; ks++) {
        int k0 = ks * 8;
        uint32_t a[2][4];
        ldmA(a[0], aU[0] + k0 * 4);
        ldmA(a[1], aU[1] + k0 * 4);
        #pragma unroll
        for (int j = 0; j < 2; j++) {           // P (E1 in CR)
            int tn = j ? t1n : t0n;
            float2 bv = *(float2*)&CR[(tn * 8 + bn8) * AP + k0 + bCol2];
            mma8(pc[0][j], a[0], bv.x, bv.y);
            mma8(pc[1][j], a[1], bv.x, bv.y);
        }
        #pragma unroll
        for (int j = 0; j < 2; j++) {           // Y half2, skip all-zero blocks
            int tn = j ? t1n : t0n;
            if (tn >= ks) {
                int ix = 64 + tn * 8 + bn8 - (lane & 3) - k0;
                float bx = sfX[ix], by = sfX[ix - 4];
                mma8(yc[0][j], a[0], bx, by);
                mma8(yc[1][j], a[1], bx, by);
            }
        }
    }
    __syncthreads();   // all E1 reads done before CR reused for P/carries

    // ---- write P frags (natural dt cols of CR) ----
    #pragma unroll
    for (int mt = 0; mt < 2; mt++)
        #pragma unroll
        for (int j = 0; j < 2; j++) {
            int tn = j ? t1n : t0n;
            int ra  = mw * 32 + mt * 16 + (lane >> 2);
            int col = tn * 8 + 2 * (lane & 3);
            *(float2*)&CR[ra * AP + col]       = make_float2(pc[mt][j][0], pc[mt][j][1]);
            *(float2*)&CR[(ra + 8) * AP + col] = make_float2(pc[mt][j][2], pc[mt][j][3]);
        }
    __syncthreads();

    // ---- parallel carry scan: 64 sequences x 64 chunks, 8 threads/sequence ----
    {
        int t = tid >> 6, seq = tid & 63;       // t uniform per warp-pair
        int bl = seq >> 5, d = seq & 31;
        float2 rl = make_float2( Inj[63 * AP + kperm(2 * d)],
                                -Inj[63 * AP + kperm(2 * d + 1)]);   // r^64
        float2 R = rl;                           // R = rl^8
        #pragma unroll
        for (int sq = 0; sq < 3; sq++) {
            float2 nR;
            nR.x = fmaf(R.x, R.x, -R.y * R.y);
            nR.y = 2.0f * R.x * R.y;
            R = nR;
        }
        float* bp = &CR[(bl * 64 + t * 8) * AP + 2 * d];
        float2 s = make_float2(0.0f, 0.0f);
        #pragma unroll
        for (int i = 0; i < 8; i++)
            s = cmad(rl, s, *(float2*)(bp + i * AP));
        Sbuf[t][seq] = s;
        __syncthreads();
        float2 X = c0S[d];
        for (int k = 0; k < t; k++)             // t uniform per warp: no divergence
            X = cmad(R, X, Sbuf[k][seq]);
        #pragma unroll
        for (int i = 0; i < 8; i++) {
            float2 p = *(float2*)(bp + i * AP);
            *(float2*)(bp + i * AP) = X;
            X = cmad(rl, X, p);
        }
    }
    __syncthreads();

    // ---- Y half1: carries x injection (K=64, dense) ----
    #pragma unroll
    for (int ks = 0; ks < 8; ks++) {
        int k0 = ks * 8;
        uint32_t a[2][4];
        ldmA(a[0], aC[0] + k0 * 4);
        ldmA(a[1], aC[1] + k0 * 4);
        #pragma unroll
        for (int j = 0; j < 2; j++) {
            int tn = j ? t1n : t0n;
            float2 bv = *(float2*)&Inj[(tn * 8 + bn8) * AP + k0 + bCol2];
            mma8(yc[0][j], a[0], bv.x, bv.y);
            mma8(yc[1][j], a[1], bv.x, bv.y);
        }
    }

    // ---- epilogue: y = Y + D*u (exact fp32) ----
    #pragma unroll
    for (int mt = 0; mt < 2; mt++)
        #pragma unroll
        for (int half = 0; half < 2; half++) {
            int r = mw * 32 + mt * 16 + (lane >> 2) + half * 8;
            float* op = out + ((size_t)((b0 + (r >> 6)) * NH + h)) * NL + (r & 63) * 64;
            #pragma unroll
            for (int j = 0; j < 2; j++) {
                int tn = j ? t1n : t0n;
                int col = tn * 8 + 2 * (lane & 3);
                float2 uv = *(float2*)&Us[r * AP + col];
                float2 o2;
                o2.x = fmaf(Dv, uv.x, yc[mt][j][half * 2 + 0]);
                o2.y = fmaf(Dv, uv.y, yc[mt][j][half * 2 + 1]);
                *(float2*)(op + col) = o2;
            }
        }
}

// ---------------------------------------------------------------------------
extern "C" void kernel_launch(void* const* d_in, const int* in_sizes, int n_in,
                              void* d_out, int out_size) {
    (void)in_sizes; (void)n_in; (void)out_size;
    const float* u     = (const float*)d_in[0];
    const float* theta = (const float*)d_in[1];
    const float* a     = (const float*)d_in[2];
    const float* Dp    = (const float*)d_in[3];
    const float* b_p   = (const float*)d_in[4];
    const float* c_p   = (const float*)d_in[5];
    const float* x0    = (const float*)d_in[6];
    float* out = (float*)d_out;

    cudaFuncSetAttribute(k_fused, cudaFuncAttributeMaxDynamicSharedMemorySize, SMEMF);
    k_fused<<<1024, 512, SMEMF>>>(u, theta, a, Dp, b_p, c_p, x0, out);
}

// round 9
// speedup vs baseline: 1.2597x; 1.2597x over previous
#include <cuda_runtime.h>
#include <cuda_fp16.h>
#include <cstdint>

#define NH 256
#define NL 4096
#define PHH 72     // Uh/CH pitch in halves (144B rows: 16B-aligned, 36 words mod 32 = 4)
#define EPH 66     // E1h/InjH pitch in halves
#define IP32 66    // Inj32 pitch in floats
#define UH_OFF  0
#define IJH_OFF 18432
#define S_OFF   26880
#define E1_OFF  (S_OFF + 16896)
#define CH_OFF  S_OFF              // overlays Inj32+E1h (dead by P-write time)
#define SMEMF   52224

static __device__ __forceinline__ uint32_t s2u(const void* p) {
    uint32_t a;
    asm("{ .reg .u64 t; cvta.to.shared.u64 t, %1; cvt.u32.u64 %0, t; }" : "=r"(a) : "l"(p));
    return a;
}
static __device__ __forceinline__ void ldmA(uint32_t* a, uint32_t addr) {
    asm volatile("ldmatrix.sync.aligned.m8n8.x4.shared.b16 {%0,%1,%2,%3}, [%4];"
                 : "=r"(a[0]), "=r"(a[1]), "=r"(a[2]), "=r"(a[3]) : "r"(addr));
}
static __device__ __forceinline__ void mma16(float* c, const uint32_t* a,
                                             uint32_t b0, uint32_t b1) {
    asm volatile(
        "mma.sync.aligned.m16n8k16.row.col.f32.f16.f16.f32 "
        "{%0,%1,%2,%3},{%4,%5,%6,%7},{%8,%9},{%0,%1,%2,%3};"
        : "+f"(c[0]), "+f"(c[1]), "+f"(c[2]), "+f"(c[3])
        : "r"(a[0]), "r"(a[1]), "r"(a[2]), "r"(a[3]), "r"(b0), "r"(b1));
}
static __device__ __forceinline__ float2 cmad(float2 m, float2 c, float2 p) {
    float2 r;
    r.x = fmaf(m.x, c.x, fmaf(-m.y, c.y, p.x));
    r.y = fmaf(m.x, c.y, fmaf( m.y, c.x, p.y));
    return r;
}
static __device__ __forceinline__ uint32_t packh2(float a, float b) {
    __half2 h = __floats2half2_rn(a, b);
    return *(uint32_t*)&h;
}

// ---------------------------------------------------------------------------
// Single fused fp16-MMA kernel. CTA = (h, b-pair), M=128 rows, 256 threads.
// Dyn SMEM: Uh[128][72]h @0 | InjH[64][66]h @18432 |
//           scratch @26880: (Inj32[64][66]f + E1h[64][66]h) then CH[128][72]h
// ---------------------------------------------------------------------------
__global__ __launch_bounds__(256, 3) void k_fused(
        const float* __restrict__ u,     const float* __restrict__ theta,
        const float* __restrict__ av_,   const float* __restrict__ Dp,
        const float* __restrict__ b_p,   const float* __restrict__ c_p,
        const float* __restrict__ x0,    float* __restrict__ out) {
    extern __shared__ char smc[];
    __half* Uh    = (__half*)(smc + UH_OFF);
    __half* IjH   = (__half*)(smc + IJH_OFF);
    float*  Inj32 = (float*)(smc + S_OFF);
    __half* E1h   = (__half*)(smc + E1_OFF);
    __half* CH    = (__half*)(smc + CH_OFF);
    __shared__ float2 swS[32];
    __shared__ float2 c0S[32];
    __shared__ float2 r64S[32];
    __shared__ float  sfX[64];
    __shared__ uint32_t Gt[128];        // half2 tables for Toeplitz B
    __shared__ float2 Sbuf[4][64];
    __shared__ float2 R8S[8][32];

    int tid  = threadIdx.x;
    int lane = tid & 31, warp = tid >> 5;
    int mw = warp & 3, nw = warp >> 2;          // 4(M) x 2(N) warp grid
    int h = blockIdx.x >> 2, b0 = (blockIdx.x & 3) * 2;
    const float T = 1.0f / (float)(NL - 1);
    float Dv = __ldg(&Dp[h]);
    uint32_t sb = s2u(smc);

    // ---- phase 0: u load + fp16 convert (8 x LDG.128 each) ----
    #pragma unroll
    for (int it = 0; it < 8; it++) {
        int idx = it * 256 + tid;
        int row = idx >> 4, c4 = (idx & 15) << 2;
        const float* src = u + ((size_t)((b0 + (row >> 6)) * NH + h)) * NL
                             + (row & 63) * 64 + c4;
        float4 v = *(const float4*)src;
        uint2 pk;
        pk.x = packh2(v.x, v.y);
        pk.y = packh2(v.z, v.w);
        *(uint2*)(Uh + row * PHH + c4) = pk;
    }

    // ---- phase A: params + short chains (warp 0) ----
    if (tid < 32) {
        int d = tid, idx = h * 32 + d;
        float av = fabsf(av_[idx]);
        float th = theta[idx];
        float er = expf(-av * T);
        float rr = er * cosf(th * T), ri = er * sinf(th * T);
        float den = av * av + th * th;
        float nr = rr - 1.0f, ni = ri;
        float t0r = (nr * -av + ni * th) / den;
        float t0i = (ni * -av - nr * th) / den;
        float q = b_p[idx] * c_p[idx];
        swS[d] = make_float2(2.0f * t0r * q, 2.0f * t0i * q);
        float g = 4.0f * T * c_p[idx] * x0[idx];
        float rm2 = rr * rr + ri * ri;
        c0S[d] = make_float2(g * rr / rm2, -g * ri / rm2);
        // r^1..r^8 natural (Re, Im)
        float pr = rr, pi = ri;
        Inj32[2 * d] = pr; Inj32[2 * d + 1] = pi;
        #pragma unroll
        for (int p = 2; p <= 8; p++) {
            float npr = fmaf(pr, rr, -pi * ri);
            float npi = fmaf(pr, ri,  pi * rr);
            pr = npr; pi = npi;
            Inj32[(p - 1) * IP32 + 2 * d]     = pr;
            Inj32[(p - 1) * IP32 + 2 * d + 1] = pi;
        }
        float qr = pr, qi = pi;                 // r^8
        R8S[0][d] = make_float2(qr, qi);
        #pragma unroll
        for (int k = 2; k <= 8; k++) {
            float nqr = fmaf(qr, pr, -qi * pi);
            float nqi = fmaf(qr, pi,  qi * pr);
            qr = nqr; qi = nqi;
            R8S[k - 1][d] = make_float2(qr, qi);
        }
    }
    __syncthreads();

    // ---- phase C: fill Inj32 rows 8..63 (1792, one cmul each) ----
    #pragma unroll
    for (int it = 0; it < 7; it++) {
        int e = it * 256 + tid;
        int i = 8 + (e >> 5), d = e & 31;
        int v = i + 1;                           // 9..64
        int k = (v - 1) >> 3, j = v - (k << 3);  // v = 8k + j, j in 1..8
        float2 A = R8S[k - 1][d];
        float bRe = Inj32[(j - 1) * IP32 + 2 * d];
        float bIm = Inj32[(j - 1) * IP32 + 2 * d + 1];
        Inj32[i * IP32 + 2 * d]     = fmaf(A.x, bRe, -A.y * bIm);
        Inj32[i * IP32 + 2 * d + 1] = fmaf(A.x, bIm,  A.y * bRe);
    }
    __syncthreads();

    // ---- phase D: r64, sfX, E1h, InjH ----
    if (tid < 32) {
        r64S[tid] = make_float2(Inj32[63 * IP32 + 2 * tid],
                                Inj32[63 * IP32 + 2 * tid + 1]);
    } else if (tid < 96) {
        int j = tid - 32;
        float s = 0.0f;
        if (j == 0) {
            #pragma unroll
            for (int d = 0; d < 32; d++) s += swS[d].x;
        } else {
            #pragma unroll
            for (int d = 0; d < 32; d++) {
                float2 w = swS[d];
                s = fmaf(w.x, Inj32[(j - 1) * IP32 + 2 * d],
                    fmaf(-w.y, Inj32[(j - 1) * IP32 + 2 * d + 1], s));
            }
        }
        sfX[j] = s;
    }
    #pragma unroll
    for (int it = 0; it < 8; it++) {             // E1h: 2048 (d,m)
        int e = it * 256 + tid;
        int d = e >> 6, m = e & 63;
        float2 w = swS[d];
        float re, im;                            // r^{63-m}
        if (m == 63) { re = 1.0f; im = 0.0f; }
        else {
            re = Inj32[(62 - m) * IP32 + 2 * d];
            im = Inj32[(62 - m) * IP32 + 2 * d + 1];
        }
        E1h[(2 * d) * EPH + m]     = __float2half_rn(fmaf(w.x, re, -w.y * im));
        E1h[(2 * d + 1) * EPH + m] = __float2half_rn(fmaf(w.x, im,  w.y * re));
    }
    #pragma unroll
    for (int it = 0; it < 8; it++) {             // InjH: 2048 (i,d); odd = -Im
        int e = it * 256 + tid;
        int i = e >> 5, d = e & 31;
        IjH[i * EPH + 2 * d]     = __float2half_rn( Inj32[i * IP32 + 2 * d]);
        IjH[i * EPH + 2 * d + 1] = __float2half_rn(-Inj32[i * IP32 + 2 * d + 1]);
    }
    __syncthreads();

    // ---- G tables for Toeplitz B: Gt[p*64+q] = half2(f[t], f[t-1]), t=2q+p-64 ----
    if (tid < 128) {
        int p = tid >> 6, qd = tid & 63;
        int t = 2 * qd + p - 64;
        float f0 = (t     >= 0) ? sfX[t]     : 0.0f;
        float f1 = (t - 1 >= 0) ? sfX[t - 1] : 0.0f;
        Gt[tid] = packh2(f0, f1);
    }
    // (no sync needed before P GEMM: P doesn't read Gt; the post-P-write
    //  __syncthreads orders Gt for Y2.)

    // ---- fragment addressing ----
    uint32_t aU[2], aC[2];
    #pragma unroll
    for (int mt = 0; mt < 2; mt++) {
        uint32_t off = (uint32_t)(mw * 32 + mt * 16 + (lane & 7) + ((lane >> 3) & 1) * 8)
                       * (PHH * 2) + ((lane >> 4) & 1) * 16;
        aU[mt] = sb + UH_OFF + off;
        aC[mt] = sb + CH_OFF + off;
    }
    int bn8 = lane >> 2, bl3 = lane & 3;

    // ---- P GEMM: P[row][dt] = sum_m U[row][m] * E1[dt][m], K=64 (4 k16 steps) ----
    {
        float pc[2][4][4];
        #pragma unroll
        for (int mt = 0; mt < 2; mt++)
            #pragma unroll
            for (int j = 0; j < 4; j++)
                #pragma unroll
                for (int q = 0; q < 4; q++) pc[mt][j][q] = 0.0f;

        #pragma unroll
        for (int ks = 0; ks < 4; ks++) {
            uint32_t a[2][4];
            ldmA(a[0], aU[0] + ks * 32);
            ldmA(a[1], aU[1] + ks * 32);
            #pragma unroll
            for (int j = 0; j < 4; j++) {
                int tn = 2 * j + nw;
                const uint32_t* bp = (const uint32_t*)
                    (E1h + (tn * 8 + bn8) * EPH + ks * 16 + 2 * bl3);
                uint32_t b0 = bp[0], b1 = bp[4];
                mma16(pc[0][j], a[0], b0, b1);
                mma16(pc[1][j], a[1], b0, b1);
            }
        }
        __syncthreads();   // E1h reads done; CH overlay now safe

        // write P frags as fp16 into CH
        #pragma unroll
        for (int mt = 0; mt < 2; mt++)
            #pragma unroll
            for (int j = 0; j < 4; j++) {
                int tn = 2 * j + nw;
                int ra  = mw * 32 + mt * 16 + bn8;
                int col = tn * 8 + 2 * bl3;
                *(uint32_t*)(CH + ra * PHH + col)       = packh2(pc[mt][j][0], pc[mt][j][1]);
                *(uint32_t*)(CH + (ra + 8) * PHH + col) = packh2(pc[mt][j][2], pc[mt][j][3]);
            }
    }
    __syncthreads();

    // ---- carry scan in CH (in place, fp16 storage / fp32 math) ----
    {
        int t = tid >> 6, seq = tid & 63;
        int bl = seq >> 5, d = seq & 31;
        float2 rl = r64S[d];
        float2 R = rl;                           // rl^16
        #pragma unroll
        for (int sq = 0; sq < 4; sq++) {
            float2 nR;
            nR.x = fmaf(R.x, R.x, -R.y * R.y);
            nR.y = 2.0f * R.x * R.y;
            R = nR;
        }
        __half* bp = CH + (bl * 64 + t * 16) * PHH + 2 * d;
        float2 s = make_float2(0.0f, 0.0f);
        #pragma unroll
        for (int i = 0; i < 16; i++) {
            float2 p = __half22float2(*(__half2*)(bp + i * PHH));
            s = cmad(rl, s, p);
        }
        Sbuf[t][seq] = s;
        __syncthreads();
        float2 X = c0S[d];
        for (int k = 0; k < t; k++)
            X = cmad(R, X, Sbuf[k][seq]);
        #pragma unroll
        for (int i = 0; i < 16; i++) {
            float2 p = __half22float2(*(__half2*)(bp + i * PHH));
            *(__half2*)(bp + i * PHH) = __floats2half2_rn(X.x, X.y);
            X = cmad(rl, X, p);
        }
    }
    __syncthreads();

    // ---- Y GEMM ----
    float yc[2][4][4];
    #pragma unroll
    for (int mt = 0; mt < 2; mt++)
        #pragma unroll
        for (int j = 0; j < 4; j++)
            #pragma unroll
            for (int q = 0; q < 4; q++) yc[mt][j][q] = 0.0f;

    // half 2: u x Toeplitz(f), triangle-skip
    #pragma unroll
    for (int ks = 0; ks < 4; ks++) {
        uint32_t a[2][4];
        ldmA(a[0], aU[0] + ks * 32);
        ldmA(a[1], aU[1] + ks * 32);
        #pragma unroll
        for (int j = 0; j < 4; j++) {
            int tn = 2 * j + nw;
            if (tn * 8 + 7 >= ks * 16) {
                int t0 = tn * 8 + bn8 - ks * 16 - 2 * bl3;
                int p  = t0 & 1;
                int q0 = (t0 + 64) >> 1;
                uint32_t b0 = Gt[p * 64 + q0];
                uint32_t b1 = Gt[p * 64 + q0 - 4];
                mma16(yc[0][j], a[0], b0, b1);
                mma16(yc[1][j], a[1], b0, b1);
            }
        }
    }
    // half 1: carries x injection
    #pragma unroll
    for (int ks = 0; ks < 4; ks++) {
        uint32_t a[2][4];
        ldmA(a[0], aC[0] + ks * 32);
        ldmA(a[1], aC[1] + ks * 32);
        #pragma unroll
        for (int j = 0; j < 4; j++) {
            int tn = 2 * j + nw;
            const uint32_t* bp = (const uint32_t*)
                (IjH + (tn * 8 + bn8) * EPH + ks * 16 + 2 * bl3);
            uint32_t b0 = bp[0], b1 = bp[4];
            mma16(yc[0][j], a[0], b0, b1);
            mma16(yc[1][j], a[1], b0, b1);
        }
    }

    // ---- epilogue: y = Y + D*u (u re-read from global, exact fp32) ----
    #pragma unroll
    for (int mt = 0; mt < 2; mt++)
        #pragma unroll
        for (int half = 0; half < 2; half++) {
            int r = mw * 32 + mt * 16 + bn8 + half * 8;
            size_t base = ((size_t)((b0 + (r >> 6)) * NH + h)) * NL + (r & 63) * 64;
            const float* up = u + base;
            float* op = out + base;
            #pragma unroll
            for (int j = 0; j < 4; j++) {
                int col = (2 * j + nw) * 8 + 2 * bl3;
                float2 uv = *(const float2*)(up + col);
                float2 o2;
                o2.x = fmaf(Dv, uv.x, yc[mt][j][half * 2 + 0]);
                o2.y = fmaf(Dv, uv.y, yc[mt][j][half * 2 + 1]);
                *(float2*)(op + col) = o2;
            }
        }
}

// ---------------------------------------------------------------------------
extern "C" void kernel_launch(void* const* d_in, const int* in_sizes, int n_in,
                              void* d_out, int out_size) {
    (void)in_sizes; (void)n_in; (void)out_size;
    const float* u     = (const float*)d_in[0];
    const float* theta = (const float*)d_in[1];
    const float* a     = (const float*)d_in[2];
    const float* Dp    = (const float*)d_in[3];
    const float* b_p   = (const float*)d_in[4];
    const float* c_p   = (const float*)d_in[5];
    const float* x0    = (const float*)d_in[6];
    float* out = (float*)d_out;

    cudaFuncSetAttribute(k_fused, cudaFuncAttributeMaxDynamicSharedMemorySize, SMEMF);
    k_fused<<<1024, 256, SMEMF>>>(u, theta, a, Dp, b_p, c_p, x0, out);
}

// round 10
// speedup vs baseline: 1.2880x; 1.0225x over previous
#include <cuda_runtime.h>
#include <cuda_fp16.h>
#include <cstdint>

#define NH 256
#define NL 4096
#define PHH 72     // Uh/CH pitch in halves (144B rows)
#define EPH 66     // E1h/InjH pitch in halves
#define IP32 66    // Inj32 pitch in floats
#define UH_OFF  0
#define IJH_OFF 18432
#define S_OFF   26880
#define E1_OFF  (S_OFF + 16896)
#define CH_OFF  S_OFF              // overlays Inj32+E1h (dead by P-write time)
#define SMEMF   52224

static __device__ __forceinline__ uint32_t s2u(const void* p) {
    uint32_t a;
    asm("{ .reg .u64 t; cvta.to.shared.u64 t, %1; cvt.u32.u64 %0, t; }" : "=r"(a) : "l"(p));
    return a;
}
static __device__ __forceinline__ void ldmA(uint32_t* a, uint32_t addr) {
    asm volatile("ldmatrix.sync.aligned.m8n8.x4.shared.b16 {%0,%1,%2,%3}, [%4];"
                 : "=r"(a[0]), "=r"(a[1]), "=r"(a[2]), "=r"(a[3]) : "r"(addr));
}
static __device__ __forceinline__ void mma16(float* c, const uint32_t* a,
                                             uint32_t b0, uint32_t b1) {
    asm volatile(
        "mma.sync.aligned.m16n8k16.row.col.f32.f16.f16.f32 "
        "{%0,%1,%2,%3},{%4,%5,%6,%7},{%8,%9},{%0,%1,%2,%3};"
        : "+f"(c[0]), "+f"(c[1]), "+f"(c[2]), "+f"(c[3])
        : "r"(a[0]), "r"(a[1]), "r"(a[2]), "r"(a[3]), "r"(b0), "r"(b1));
}
static __device__ __forceinline__ float2 cmad(float2 m, float2 c, float2 p) {
    float2 r;
    r.x = fmaf(m.x, c.x, fmaf(-m.y, c.y, p.x));
    r.y = fmaf(m.x, c.y, fmaf( m.y, c.x, p.y));
    return r;
}
static __device__ __forceinline__ uint32_t packh2(float a, float b) {
    __half2 h = __floats2half2_rn(a, b);
    return *(uint32_t*)&h;
}

// ---------------------------------------------------------------------------
// Single fused fp16-MMA kernel. CTA = (h, b-pair), M=128 rows, 256 threads.
// Dyn SMEM: Uh[128][72]h @0 | InjH[64][66]h @18432 |
//           scratch @26880: (Inj32[64][66]f + E1h[64][66]h) then CH[128][72]h
// ---------------------------------------------------------------------------
__global__ __launch_bounds__(256, 4) void k_fused(
        const float* __restrict__ u,     const float* __restrict__ theta,
        const float* __restrict__ av_,   const float* __restrict__ Dp,
        const float* __restrict__ b_p,   const float* __restrict__ c_p,
        const float* __restrict__ x0,    float* __restrict__ out) {
    extern __shared__ char smc[];
    __half* Uh    = (__half*)(smc + UH_OFF);
    __half* IjH   = (__half*)(smc + IJH_OFF);
    float*  Inj32 = (float*)(smc + S_OFF);
    __half* E1h   = (__half*)(smc + E1_OFF);
    __half* CH    = (__half*)(smc + CH_OFF);
    __shared__ float2 swS[32];
    __shared__ float2 c0S[32];
    __shared__ float2 r64S[32];
    __shared__ float  sfX[64];
    __shared__ uint32_t Gt[128];        // half2 tables for Toeplitz B
    __shared__ float2 Sbuf[4][64];
    __shared__ float2 R8S[8][32];

    int tid  = threadIdx.x;
    int lane = tid & 31, warp = tid >> 5;
    int mw = warp & 3, nw = warp >> 2;          // 4(M) x 2(N) warp grid
    int h = blockIdx.x >> 2, b0 = (blockIdx.x & 3) * 2;
    const float T = 1.0f / (float)(NL - 1);
    float Dv = __ldg(&Dp[h]);
    uint32_t sb = s2u(smc);

    // ---- phase 0: u load + fp16 convert ----
    #pragma unroll
    for (int it = 0; it < 8; it++) {
        int idx = it * 256 + tid;
        int row = idx >> 4, c4 = (idx & 15) << 2;
        const float* src = u + ((size_t)((b0 + (row >> 6)) * NH + h)) * NL
                             + (row & 63) * 64 + c4;
        float4 v = *(const float4*)src;
        uint2 pk;
        pk.x = packh2(v.x, v.y);
        pk.y = packh2(v.z, v.w);
        *(uint2*)(Uh + row * PHH + c4) = pk;
    }

    // ---- phase A: params + short chains (warp 0 only) ----
    if (tid < 32) {
        int d = tid, idx = h * 32 + d;
        float av = fabsf(av_[idx]);
        float th = theta[idx];
        float er = expf(-av * T);
        float rr = er * cosf(th * T), ri = er * sinf(th * T);
        float den = av * av + th * th;
        float nr = rr - 1.0f, ni = ri;
        float t0r = (nr * -av + ni * th) / den;
        float t0i = (ni * -av - nr * th) / den;
        float q = b_p[idx] * c_p[idx];
        swS[d] = make_float2(2.0f * t0r * q, 2.0f * t0i * q);
        float g = 4.0f * T * c_p[idx] * x0[idx];
        float rm2 = rr * rr + ri * ri;
        c0S[d] = make_float2(g * rr / rm2, -g * ri / rm2);
        // r^1..r^8 natural (Re, Im)
        float pr = rr, pi = ri;
        Inj32[2 * d] = pr; Inj32[2 * d + 1] = pi;
        #pragma unroll
        for (int p = 2; p <= 8; p++) {
            float npr = fmaf(pr, rr, -pi * ri);
            float npi = fmaf(pr, ri,  pi * rr);
            pr = npr; pi = npi;
            Inj32[(p - 1) * IP32 + 2 * d]     = pr;
            Inj32[(p - 1) * IP32 + 2 * d + 1] = pi;
        }
        float qr = pr, qi = pi;                 // r^8
        R8S[0][d] = make_float2(qr, qi);
        #pragma unroll
        for (int k = 2; k <= 8; k++) {
            float nqr = fmaf(qr, pr, -qi * pi);
            float nqi = fmaf(qr, pi,  qi * pr);
            qr = nqr; qi = nqi;
            R8S[k - 1][d] = make_float2(qr, qi);
        }
    }
    __syncthreads();

    // ---- fused table pass: Inj32 rows 8..63 + InjH + E1h + r64S, one sweep ----
    #pragma unroll
    for (int it = 0; it < 8; it++) {
        int e = it * 256 + tid;                  // 2048 (i, d)
        int i = e >> 5, d = e & 31;
        float2 w = swS[d];
        float re, im;                            // r^{i+1}
        if (i < 8) {
            re = Inj32[i * IP32 + 2 * d];
            im = Inj32[i * IP32 + 2 * d + 1];
        } else {
            int v = i + 1;                       // 9..64
            int k = (v - 1) >> 3, j = v - (k << 3);
            float2 A = R8S[k - 1][d];
            float bRe = Inj32[(j - 1) * IP32 + 2 * d];
            float bIm = Inj32[(j - 1) * IP32 + 2 * d + 1];
            re = fmaf(A.x, bRe, -A.y * bIm);
            im = fmaf(A.x, bIm,  A.y * bRe);
            Inj32[i * IP32 + 2 * d]     = re;
            Inj32[i * IP32 + 2 * d + 1] = im;
        }
        *(uint32_t*)(IjH + i * EPH + 2 * d) = packh2(re, -im);
        if (i < 63) {
            int m = 62 - i;                      // E1[dt][m] uses r^{63-m}
            E1h[(2 * d) * EPH + m]     = __float2half_rn(fmaf(w.x, re, -w.y * im));
            E1h[(2 * d + 1) * EPH + m] = __float2half_rn(fmaf(w.x, im,  w.y * re));
        } else {
            E1h[(2 * d) * EPH + 63]     = __float2half_rn(w.x);   // m=63: r^0 = 1
            E1h[(2 * d + 1) * EPH + 63] = __float2half_rn(w.y);
            r64S[d] = make_float2(re, im);
        }
    }
    __syncthreads();

    // ---- sfX: f[j] = Re sum_d w_d r_d^j, 4 threads per j + shfl reduce ----
    {
        int j = tid >> 2, dg = tid & 3;
        float s = 0.0f;
        #pragma unroll
        for (int dd = 0; dd < 8; dd++) {
            int d = dg * 8 + dd;
            float2 w = swS[d];
            float re, im;
            if (j == 0) { re = 1.0f; im = 0.0f; }
            else {
                re = Inj32[(j - 1) * IP32 + 2 * d];
                im = Inj32[(j - 1) * IP32 + 2 * d + 1];
            }
            s = fmaf(w.x, re, fmaf(-w.y, im, s));
        }
        s += __shfl_xor_sync(0xFFFFFFFFu, s, 1);
        s += __shfl_xor_sync(0xFFFFFFFFu, s, 2);
        if (dg == 0) sfX[j] = s;
    }
    __syncthreads();
    // ---- Gt: half2(f[t], f[t-1]), t = 2q + p - 64 ----
    if (tid < 128) {
        int p = tid >> 6, qd = tid & 63;
        int t = 2 * qd + p - 64;
        float f0 = (t     >= 0) ? sfX[t]     : 0.0f;
        float f1 = (t - 1 >= 0) ? sfX[t - 1] : 0.0f;
        Gt[tid] = packh2(f0, f1);
    }
    // (Gt ordered for Y2 by the post-P-write __syncthreads)

    // ---- fragment addressing ----
    uint32_t aU[2], aC[2];
    #pragma unroll
    for (int mt = 0; mt < 2; mt++) {
        uint32_t off = (uint32_t)(mw * 32 + mt * 16 + (lane & 7) + ((lane >> 3) & 1) * 8)
                       * (PHH * 2) + ((lane >> 4) & 1) * 16;
        aU[mt] = sb + UH_OFF + off;
        aC[mt] = sb + CH_OFF + off;
    }
    int bn8 = lane >> 2, bl3 = lane & 3;

    // ---- P GEMM: P[row][dt] = sum_m U[row][m] * E1[dt][m], K=64 ----
    {
        float pc[2][4][4];
        #pragma unroll
        for (int mt = 0; mt < 2; mt++)
            #pragma unroll
            for (int j = 0; j < 4; j++)
                #pragma unroll
                for (int q = 0; q < 4; q++) pc[mt][j][q] = 0.0f;

        #pragma unroll
        for (int ks = 0; ks < 4; ks++) {
            uint32_t a[2][4];
            ldmA(a[0], aU[0] + ks * 32);
            ldmA(a[1], aU[1] + ks * 32);
            #pragma unroll
            for (int j = 0; j < 4; j++) {
                int tn = 2 * j + nw;
                const uint32_t* bp = (const uint32_t*)
                    (E1h + (tn * 8 + bn8) * EPH + ks * 16 + 2 * bl3);
                uint32_t b0 = bp[0], b1 = bp[4];
                mma16(pc[0][j], a[0], b0, b1);
                mma16(pc[1][j], a[1], b0, b1);
            }
        }
        __syncthreads();   // E1h reads done; CH overlay now safe

        #pragma unroll
        for (int mt = 0; mt < 2; mt++)
            #pragma unroll
            for (int j = 0; j < 4; j++) {
                int tn = 2 * j + nw;
                int ra  = mw * 32 + mt * 16 + bn8;
                int col = tn * 8 + 2 * bl3;
                *(uint32_t*)(CH + ra * PHH + col)       = packh2(pc[mt][j][0], pc[mt][j][1]);
                *(uint32_t*)(CH + (ra + 8) * PHH + col) = packh2(pc[mt][j][2], pc[mt][j][3]);
            }
    }
    __syncthreads();

    // ---- carry scan in CH: chunk values register-resident ----
    {
        int t = tid >> 6, seq = tid & 63;
        int bl = seq >> 5, d = seq & 31;
        float2 rl = r64S[d];
        float2 R = rl;                           // rl^16
        #pragma unroll
        for (int sq = 0; sq < 4; sq++) {
            float2 nR;
            nR.x = fmaf(R.x, R.x, -R.y * R.y);
            nR.y = 2.0f * R.x * R.y;
            R = nR;
        }
        __half* bp = CH + (bl * 64 + t * 16) * PHH + 2 * d;
        float2 p[16];
        #pragma unroll
        for (int i = 0; i < 16; i++)
            p[i] = __half22float2(*(__half2*)(bp + i * PHH));
        float2 s = make_float2(0.0f, 0.0f);
        #pragma unroll
        for (int i = 0; i < 16; i++)
            s = cmad(rl, s, p[i]);
        Sbuf[t][seq] = s;
        __syncthreads();
        float2 X = c0S[d];
        for (int k = 0; k < t; k++)             // t uniform per warp
            X = cmad(R, X, Sbuf[k][seq]);
        #pragma unroll
        for (int i = 0; i < 16; i++) {
            *(__half2*)(bp + i * PHH) = __floats2half2_rn(X.x, X.y);
            X = cmad(rl, X, p[i]);
        }
    }
    __syncthreads();

    // ---- Y GEMM ----
    float yc[2][4][4];
    #pragma unroll
    for (int mt = 0; mt < 2; mt++)
        #pragma unroll
        for (int j = 0; j < 4; j++)
            #pragma unroll
            for (int q = 0; q < 4; q++) yc[mt][j][q] = 0.0f;

    // half 2: u x Toeplitz(f), triangle-skip
    #pragma unroll
    for (int ks = 0; ks < 4; ks++) {
        uint32_t a[2][4];
        ldmA(a[0], aU[0] + ks * 32);
        ldmA(a[1], aU[1] + ks * 32);
        #pragma unroll
        for (int j = 0; j < 4; j++) {
            int tn = 2 * j + nw;
            if (tn * 8 + 7 >= ks * 16) {
                int t0 = tn * 8 + bn8 - ks * 16 - 2 * bl3;
                int p  = t0 & 1;
                int q0 = (t0 + 64) >> 1;
                uint32_t b0 = Gt[p * 64 + q0];
                uint32_t b1 = Gt[p * 64 + q0 - 4];
                mma16(yc[0][j], a[0], b0, b1);
                mma16(yc[1][j], a[1], b0, b1);
            }
        }
    }
    // half 1: carries x injection
    #pragma unroll
    for (int ks = 0; ks < 4; ks++) {
        uint32_t a[2][4];
        ldmA(a[0], aC[0] + ks * 32);
        ldmA(a[1], aC[1] + ks * 32);
        #pragma unroll
        for (int j = 0; j < 4; j++) {
            int tn = 2 * j + nw;
            const uint32_t* bp = (const uint32_t*)
                (IjH + (tn * 8 + bn8) * EPH + ks * 16 + 2 * bl3);
            uint32_t b0 = bp[0], b1 = bp[4];
            mma16(yc[0][j], a[0], b0, b1);
            mma16(yc[1][j], a[1], b0, b1);
        }
    }

    // ---- epilogue: y = Y + D*u (u re-read from global, exact fp32) ----
    #pragma unroll
    for (int mt = 0; mt < 2; mt++)
        #pragma unroll
        for (int half = 0; half < 2; half++) {
            int r = mw * 32 + mt * 16 + bn8 + half * 8;
            size_t base = ((size_t)((b0 + (r >> 6)) * NH + h)) * NL + (r & 63) * 64;
            const float* up = u + base;
            float* op = out + base;
            #pragma unroll
            for (int j = 0; j < 4; j++) {
                int col = (2 * j + nw) * 8 + 2 * bl3;
                float2 uv = *(const float2*)(up + col);
                float2 o2;
                o2.x = fmaf(Dv, uv.x, yc[mt][j][half * 2 + 0]);
                o2.y = fmaf(Dv, uv.y, yc[mt][j][half * 2 + 1]);
                *(float2*)(op + col) = o2;
            }
        }
}

// ---------------------------------------------------------------------------
extern "C" void kernel_launch(void* const* d_in, const int* in_sizes, int n_in,
                              void* d_out, int out_size) {
    (void)in_sizes; (void)n_in; (void)out_size;
    const float* u     = (const float*)d_in[0];
    const float* theta = (const float*)d_in[1];
    const float* a     = (const float*)d_in[2];
    const float* Dp    = (const float*)d_in[3];
    const float* b_p   = (const float*)d_in[4];
    const float* c_p   = (const float*)d_in[5];
    const float* x0    = (const float*)d_in[6];
    float* out = (float*)d_out;

    cudaFuncSetAttribute(k_fused, cudaFuncAttributeMaxDynamicSharedMemorySize, SMEMF);
    k_fused<<<1024, 256, SMEMF>>>(u, theta, a, Dp, b_p, c_p, x0, out);
}